// round 11
// baseline (speedup 1.0000x reference)
#include <cuda_runtime.h>
#include <cuda_bf16.h>
#include <cstdint>

#define EPSF 1e-8f
static constexpr int B_  = 8;
static constexpr int N_  = 256;
static constexpr int NF_ = 2048;

__device__ __nv_bfloat16 g_K[B_ * N_ * N_];   // bf16 K (fallback only)
__device__ float g_p  [B_ * N_];              // softmax(gamma) (fallback only)
__device__ float g_u2 [B_ * N_];
__device__ float g_cp [B_ * N_];              // coupling accumulator per row
__device__ float g_S  [B_];
__device__ float g_bound[B_];                 // upper bound on max_j KTu_j
__device__ int   g_conv[B_];                  // 1 = fast-path certificate failed

#define GRIDDEP_WAIT() asm volatile("griddepcontrol.wait;" ::: "memory")

// ---------------------------------------------------------------------------
// helpers
// ---------------------------------------------------------------------------
__device__ __forceinline__ void unpack8(uint4 kr, float* f)
{
    float2 f0 = __bfloat1622float2(*reinterpret_cast<__nv_bfloat162*>(&kr.x));
    float2 f1 = __bfloat1622float2(*reinterpret_cast<__nv_bfloat162*>(&kr.y));
    float2 f2 = __bfloat1622float2(*reinterpret_cast<__nv_bfloat162*>(&kr.z));
    float2 f3 = __bfloat1622float2(*reinterpret_cast<__nv_bfloat162*>(&kr.w));
    f[0] = f0.x; f[1] = f0.y; f[2] = f1.x; f[3] = f1.y;
    f[4] = f2.x; f[5] = f2.y; f[6] = f3.x; f[7] = f3.y;
}

__device__ __forceinline__ float dot8(uint4 kr, const float* vj)
{
    float kf[8];
    unpack8(kr, kf);
    float acc = 0.f;
#pragma unroll
    for (int x = 0; x < 8; ++x) acc = fmaf(kf[x], vj[x], acc);
    return acc;
}

// 256-thread broadcast sum (fallback path)
__device__ __forceinline__ float blk_sum256(float val, float* red)
{
#pragma unroll
    for (int o = 16; o; o >>= 1) val += __shfl_xor_sync(0xffffffffu, val, o);
    if ((threadIdx.x & 31) == 0) red[threadIdx.x >> 5] = val;
    __syncthreads();
    if (threadIdx.x < 32) {
        float s = (threadIdx.x < 8) ? red[threadIdx.x] : 0.f;
#pragma unroll
        for (int o = 4; o; o >>= 1) s += __shfl_xor_sync(0xffffffffu, s, o);
        if (threadIdx.x == 0) red[8] = s;
    }
    __syncthreads();
    float r = red[8];
    __syncthreads();
    return r;
}

// ---------------------------------------------------------------------------
// Kernel 1: pooling -> K row (bf16) AND the full fast-path Sinkhorn+coupling:
//  round1: (sum w, sum exp(gamma))
//  K = (W+EPS)^10 ; s_t = K_t * sin(theta_t - theta_I - alpha_It)
//  round2: (sum K, sum s, max K)
//  u1 = p/(rsK/256+EPS); v1 = q/EPS (uniform, certified later via bound);
//  Kv1 = v1*rsK; u2 = p/(Kv1+EPS); conv check u2==u1; cp = v1*Σ s;
//  atomicAdd S += u2*Kv1; atomicAdd bound += maxK*u1.
// Grid (256,8), 256 threads, <=32 regs target (8 CTAs/SM).
// ---------------------------------------------------------------------------
__global__ void __launch_bounds__(256, 8) pool_build_k(
    const float* __restrict__ A, const float* __restrict__ gamma_g,
    const float* __restrict__ theta_g, const float* __restrict__ alpha_g)
{
    const int I = blockIdx.x, b = blockIdx.y;
    const int t = threadIdx.x;
    const int wd = t >> 5, lane = t & 31;
    const float* base = A + ((size_t)b * NF_ + (size_t)I * 8) * NF_;

    // small input loads (L2-resident after first touch), issued early
    float gmine = gamma_g[b * N_ + t];
    float thmine = theta_g[b * N_ + t];
    float alp   = __ldg(&alpha_g[(size_t)I * N_ + t]);
    float gI    = __ldg(&gamma_g[b * N_ + I]);
    float tI    = __ldg(&theta_g[b * N_ + I]);

    // direct block-column accumulation: cols [8t, 8t+8) over 8 rows
    const float4* rp = reinterpret_cast<const float4*>(base) + 2 * t;
    float acc0 = 0.f, acc1 = 0.f;
#pragma unroll
    for (int r = 0; r < 8; ++r) {
        float4 f0 = __ldcs(rp + (size_t)r * 512);
        float4 f1 = __ldcs(rp + (size_t)r * 512 + 1);
        acc0 += (f0.x + f0.y) + (f0.z + f0.w);
        acc1 += (f1.x + f1.y) + (f1.z + f1.w);
    }
    float w = fmaxf((acc0 + acc1) * (1.0f / 64.0f), 0.0f);   // relu(A_lat[I,t])
    float e = expf(gmine);                                    // no-max softmax

    __shared__ float rA[9], rB[9], rC[9], rD[9], rE[9];

    // ---- round 1: (sum w, sum exp) ----
    {
        float sv = w, ev = e;
#pragma unroll
        for (int o = 16; o; o >>= 1) {
            sv += __shfl_xor_sync(0xffffffffu, sv, o);
            ev += __shfl_xor_sync(0xffffffffu, ev, o);
        }
        if (lane == 0) { rA[wd] = sv; rB[wd] = ev; }
    }
    __syncthreads();
    if (t < 32) {
        float s = (t < 8) ? rA[t] : 0.f;
        float v = (t < 8) ? rB[t] : 0.f;
#pragma unroll
        for (int o = 4; o; o >>= 1) {
            s += __shfl_xor_sync(0xffffffffu, s, o);
            v += __shfl_xor_sync(0xffffffffu, v, o);
        }
        if (t == 0) { rA[8] = s; rB[8] = v; }
    }
    __syncthreads();
    const float rowsum = rA[8], esum = rB[8];

    float W = (rowsum > EPSF) ? (w / (rowsum + EPSF)) : (1.0f / N_);
    float x  = W + EPSF;
    float x2 = x * x, x4 = x2 * x2, x8 = x4 * x4;
    __nv_bfloat16 kb = __float2bfloat16(x8 * x2);   // K = x^10 (bf16)
    g_K[((size_t)b * N_ + I) * N_ + t] = kb;

    float kf = __bfloat162float(kb);
    float sn = kf * __sinf(thmine - tI - alp);      // K_It * sin(th_t - th_I - a_It)

    // ---- round 2: (sum K, sum sin-term, max K) ----
    {
        float sv = kf, cv = sn, mv = kf;
#pragma unroll
        for (int o = 16; o; o >>= 1) {
            sv += __shfl_xor_sync(0xffffffffu, sv, o);
            cv += __shfl_xor_sync(0xffffffffu, cv, o);
            mv  = fmaxf(mv, __shfl_xor_sync(0xffffffffu, mv, o));
        }
        if (lane == 0) { rC[wd] = sv; rD[wd] = cv; rE[wd] = mv; }
    }
    __syncthreads();
    if (t == 0) {
        float rsK = 0.f, cps = 0.f, mk = 0.f;
#pragma unroll
        for (int i = 0; i < 8; ++i) {
            rsK += rC[i];
            cps += rD[i];
            mk   = fmaxf(mk, rE[i]);
        }
        const float q  = 1.0f / N_;
        const float v1 = q / EPSF;                  // uniform v1 (certified by bound)
        float pI  = expf(gI) / esum;
        float u1  = pI / (rsK * q + EPSF);          // true first u (Kv0 = rsK/256)
        float kv1 = v1 * rsK;
        float u2  = pI / (kv1 + EPSF);
        if (u2 != u1) g_conv[b] = 1;                // certificate failed
        const int gi = b * N_ + I;
        g_p [gi] = pI;                               // fallback input
        g_u2[gi] = u2;
        g_cp[gi] = v1 * cps;
        atomicAdd(&g_S[b], u2 * kv1);
        atomicAdd(&g_bound[b], mk * u1);            // >= max_j KTu_j contribution
    }
}

// ---------------------------------------------------------------------------
// Kernel 2: final output. PDL: preload inputs, wait, then read g_*.
// Fast path (both certificates hold): pointwise output.
// Fallback: faithful 10-iter Sinkhorn + coupling from g_K / g_p.
// Grid 8, 256 threads.
// ---------------------------------------------------------------------------
__global__ void __launch_bounds__(256) kfinal(
    const float* __restrict__ theta_g, const float* __restrict__ gamma_g,
    const float* __restrict__ omega_g, const float* __restrict__ alpha_g,
    const float* __restrict__ logk_g,  float* __restrict__ out)
{
    __shared__ float red[10];
    __shared__ float vsh[256], tsh[256], p_s[256], u_s[256], kv_s[256];

    const int b = blockIdx.x;
    const int t = threadIdx.x;

    // ---- prolog: input loads independent of pool's writes ----
    float ti  = theta_g[b * N_ + t];
    float ga  = gamma_g[b * N_ + t];
    float om  = omega_g[t];
    float kap = log1pf(expf(logk_g[t]));                    // softplus

    // ---- wait for pool completion (PDL) ----
    GRIDDEP_WAIT();

    const float bound = g_bound[b];
    const int fast = (g_conv[b] == 0) && (bound + EPSF == EPSF);

    if (fast) {
        // -------- converged fast path --------
        float S    = g_S[b];
        float Sinv = 1.0f / (S + EPSF);
        float u2   = g_u2[b * N_ + t];
        float cp   = g_cp[b * N_ + t];
        float td   = om + u2 * Sinv * cp + kap * (ga - ti);
        out[b * N_ + t] = ti + td;                          // DT=1, K_COUP=1
    } else {
        // -------- fallback: faithful 10-iter Sinkhorn from scratch --------
        const int wd = t >> 5, lane = t & 31;
        p_s[t] = g_p[b * N_ + t];
        u_s[t] = 1.0f / N_;
        vsh[t] = 1.0f / N_;
        tsh[t] = ti;
        __syncthreads();

        for (int it = 0; it < 10; ++it) {
            // u-update: 8 warps x 32 rows, K from L2
#pragma unroll 1
            for (int k = 0; k < 32; ++k) {
                int ii = wd * 32 + k;
                uint4 kr = reinterpret_cast<const uint4*>(g_K + ((size_t)b * N_ + ii) * N_)[lane];
                float acc = dot8(kr, &vsh[lane * 8]);
#pragma unroll
                for (int o = 16; o; o >>= 1) acc += __shfl_xor_sync(0xffffffffu, acc, o);
                if (lane == 0) u_s[ii] = p_s[ii] / (acc + EPSF);
            }
            __syncthreads();
            // v-update: thread t = column j
            float s = 0.f;
#pragma unroll 1
            for (int ii = 0; ii < N_; ++ii)
                s = fmaf(__bfloat162float(g_K[((size_t)b * N_ + ii) * N_ + t]), u_s[ii], s);
            __syncthreads();
            vsh[t] = (1.0f / N_) / (s + EPSF);
            __syncthreads();
        }

        // final Kv, S
#pragma unroll 1
        for (int k = 0; k < 32; ++k) {
            int ii = wd * 32 + k;
            uint4 kr = reinterpret_cast<const uint4*>(g_K + ((size_t)b * N_ + ii) * N_)[lane];
            float acc = dot8(kr, &vsh[lane * 8]);
#pragma unroll
            for (int o = 16; o; o >>= 1) acc += __shfl_xor_sync(0xffffffffu, acc, o);
            if (lane == 0) kv_s[ii] = acc;
        }
        __syncthreads();
        float S = blk_sum256(u_s[t] * kv_s[t], red);
        float Sinv = 1.0f / (S + EPSF);

        // coupling: thread t = row i
        float acc = 0.f;
#pragma unroll 1
        for (int j = 0; j < N_; ++j) {
            float kv = __bfloat162float(g_K[((size_t)b * N_ + t) * N_ + j]) * vsh[j];
            float d  = tsh[j] - ti - alpha_g[(size_t)t * N_ + j];
            acc = fmaf(kv, __sinf(d), acc);
        }
        float td = om + u_s[t] * Sinv * acc + kap * (ga - ti);
        out[b * N_ + t] = ti + td;
    }

    // -------- housekeeping for next graph replay --------
    __syncthreads();
    if (t == 0) { g_S[b] = 0.f; g_bound[b] = 0.f; g_conv[b] = 0; }
}

// ---------------------------------------------------------------------------
extern "C" void kernel_launch(void* const* d_in, const int* in_sizes, int n_in,
                              void* d_out, int out_size)
{
    const float* theta = (const float*)d_in[0];
    const float* gamma = (const float*)d_in[1];
    const float* A     = (const float*)d_in[2];
    const float* omega = (const float*)d_in[3];
    const float* alpha = (const float*)d_in[4];
    const float* logk  = (const float*)d_in[5];
    float* out = (float*)d_out;

    dim3 g1(256, 8);
    pool_build_k<<<g1, 256>>>(A, gamma, theta, alpha);

    // kfinal with PDL: overlaps its prolog with pool's execution
    {
        cudaLaunchConfig_t cfg = {};
        cfg.gridDim  = dim3(B_);
        cfg.blockDim = dim3(256);
        cudaLaunchAttribute at[1];
        at[0].id = cudaLaunchAttributeProgrammaticStreamSerialization;
        at[0].val.programmaticStreamSerializationAllowed = 1;
        cfg.attrs = at;
        cfg.numAttrs = 1;
        cudaLaunchKernelEx(&cfg, kfinal, theta, gamma, omega, alpha, logk, out);
    }
}

// round 12
// speedup vs baseline: 8.6092x; 8.6092x over previous
#include <cuda_runtime.h>
#include <cuda_bf16.h>
#include <cstdint>

#define EPSF 1e-8f
static constexpr int B_  = 8;
static constexpr int N_  = 256;
static constexpr int NF_ = 2048;

__device__ __nv_bfloat16 g_K[B_ * N_ * N_];   // bf16 K, L2-resident
__device__ float g_KTu[B_ * N_];              // exact K^T u1 (kmid), reset by kfinal
__device__ float g_p  [B_ * N_];
__device__ float g_u1 [B_ * N_];
__device__ float g_u2 [B_ * N_];
__device__ float g_cp [B_ * N_];              // coupling accumulator per row
__device__ float g_S  [B_];
__device__ int   g_conv[B_];                  // 1 = row fixed-point check failed

#define GRIDDEP_WAIT() asm volatile("griddepcontrol.wait;" ::: "memory")

// ---------------------------------------------------------------------------
// helpers
// ---------------------------------------------------------------------------
__device__ __forceinline__ void unpack8(uint4 kr, float* f)
{
    float2 f0 = __bfloat1622float2(*reinterpret_cast<__nv_bfloat162*>(&kr.x));
    float2 f1 = __bfloat1622float2(*reinterpret_cast<__nv_bfloat162*>(&kr.y));
    float2 f2 = __bfloat1622float2(*reinterpret_cast<__nv_bfloat162*>(&kr.z));
    float2 f3 = __bfloat1622float2(*reinterpret_cast<__nv_bfloat162*>(&kr.w));
    f[0] = f0.x; f[1] = f0.y; f[2] = f1.x; f[3] = f1.y;
    f[4] = f2.x; f[5] = f2.y; f[6] = f3.x; f[7] = f3.y;
}

__device__ __forceinline__ float dot8(uint4 kr, const float* vj)
{
    float kf[8];
    unpack8(kr, kf);
    float acc = 0.f;
#pragma unroll
    for (int x = 0; x < 8; ++x) acc = fmaf(kf[x], vj[x], acc);
    return acc;
}

// 256-thread broadcast sum (fallback path)
__device__ __forceinline__ float blk_sum256(float val, float* red)
{
#pragma unroll
    for (int o = 16; o; o >>= 1) val += __shfl_xor_sync(0xffffffffu, val, o);
    if ((threadIdx.x & 31) == 0) red[threadIdx.x >> 5] = val;
    __syncthreads();
    if (threadIdx.x < 32) {
        float s = (threadIdx.x < 8) ? red[threadIdx.x] : 0.f;
#pragma unroll
        for (int o = 4; o; o >>= 1) s += __shfl_xor_sync(0xffffffffu, s, o);
        if (threadIdx.x == 0) red[8] = s;
    }
    __syncthreads();
    float r = red[8];
    __syncthreads();
    return r;
}

// ---------------------------------------------------------------------------
// Kernel 1: pooling -> K row (bf16) + row-local fast-path precompute.
//  round1: (sum w, sum exp(gamma))
//  K = (W+EPS)^10 ; s_t = K_t * sin(theta_t - theta_I - alpha_It)
//  round2: (sum K, sum s)
//  u1 = p/(rsK/256+EPS); v1 := q/EPS (validity certified EXACTLY by kfinal);
//  kv1 = v1*rsK; u2 = p/(kv1+EPS); row check u2==u1; cp = v1*Σs; S += u2*kv1.
// NO per-column atomics here (they cost ~6us of LTS serialization).
// Grid (256,8), 256 threads, <=32 regs (8 CTAs/SM).
// ---------------------------------------------------------------------------
__global__ void __launch_bounds__(256, 8) pool_build_k(
    const float* __restrict__ A, const float* __restrict__ gamma_g,
    const float* __restrict__ theta_g, const float* __restrict__ alpha_g)
{
    const int I = blockIdx.x, b = blockIdx.y;
    const int t = threadIdx.x;
    const int wd = t >> 5, lane = t & 31;
    const float* base = A + ((size_t)b * NF_ + (size_t)I * 8) * NF_;

    // small input loads (L2-resident after first touch), issued early
    float gmine  = gamma_g[b * N_ + t];
    float thmine = theta_g[b * N_ + t];
    float alp    = __ldg(&alpha_g[(size_t)I * N_ + t]);
    float gI     = __ldg(&gamma_g[b * N_ + I]);
    float tI     = __ldg(&theta_g[b * N_ + I]);

    // direct block-column accumulation: cols [8t, 8t+8) over 8 rows
    const float4* rp = reinterpret_cast<const float4*>(base) + 2 * t;
    float acc0 = 0.f, acc1 = 0.f;
#pragma unroll
    for (int r = 0; r < 8; ++r) {
        float4 f0 = __ldcs(rp + (size_t)r * 512);
        float4 f1 = __ldcs(rp + (size_t)r * 512 + 1);
        acc0 += (f0.x + f0.y) + (f0.z + f0.w);
        acc1 += (f1.x + f1.y) + (f1.z + f1.w);
    }
    float w = fmaxf((acc0 + acc1) * (1.0f / 64.0f), 0.0f);   // relu(A_lat[I,t])
    float e = expf(gmine);                                    // no-max softmax

    __shared__ float rA[9], rB[9], rC[9], rD[9];

    // ---- round 1: (sum w, sum exp) ----
    {
        float sv = w, ev = e;
#pragma unroll
        for (int o = 16; o; o >>= 1) {
            sv += __shfl_xor_sync(0xffffffffu, sv, o);
            ev += __shfl_xor_sync(0xffffffffu, ev, o);
        }
        if (lane == 0) { rA[wd] = sv; rB[wd] = ev; }
    }
    __syncthreads();
    if (t < 32) {
        float s = (t < 8) ? rA[t] : 0.f;
        float v = (t < 8) ? rB[t] : 0.f;
#pragma unroll
        for (int o = 4; o; o >>= 1) {
            s += __shfl_xor_sync(0xffffffffu, s, o);
            v += __shfl_xor_sync(0xffffffffu, v, o);
        }
        if (t == 0) { rA[8] = s; rB[8] = v; }
    }
    __syncthreads();
    const float rowsum = rA[8], esum = rB[8];

    float W = (rowsum > EPSF) ? (w / (rowsum + EPSF)) : (1.0f / N_);
    float x  = W + EPSF;
    float x2 = x * x, x4 = x2 * x2, x8 = x4 * x4;
    __nv_bfloat16 kb = __float2bfloat16(x8 * x2);   // K = x^10 (bf16)
    g_K[((size_t)b * N_ + I) * N_ + t] = kb;

    float kf = __bfloat162float(kb);
    float sn = kf * __sinf(thmine - tI - alp);      // K_It * sin(th_t - th_I - a_It)

    // ---- round 2: (sum K, sum sin-term) ----
    {
        float sv = kf, cv = sn;
#pragma unroll
        for (int o = 16; o; o >>= 1) {
            sv += __shfl_xor_sync(0xffffffffu, sv, o);
            cv += __shfl_xor_sync(0xffffffffu, cv, o);
        }
        if (lane == 0) { rC[wd] = sv; rD[wd] = cv; }
    }
    __syncthreads();
    if (t == 0) {
        float rsK = 0.f, cps = 0.f;
#pragma unroll
        for (int i = 0; i < 8; ++i) { rsK += rC[i]; cps += rD[i]; }

        const float q  = 1.0f / N_;
        const float v1 = q / EPSF;                  // uniform v1 (certified in kfinal)
        float pI  = expf(gI) / esum;
        float u1  = pI / (rsK * q + EPSF);          // true first u (Kv0 = rsK/256)
        float kv1 = v1 * rsK;
        float u2  = pI / (kv1 + EPSF);
        if (u2 != u1) g_conv[b] = 1;                // row fixed-point check failed

        const int gi = b * N_ + I;
        g_p [gi] = pI;
        g_u1[gi] = u1;
        g_u2[gi] = u2;
        g_cp[gi] = v1 * cps;
        atomicAdd(&g_S[b], u2 * kv1);
    }
}

// ---------------------------------------------------------------------------
// Kernel 2 (kmid): exact KTu = K^T u1. Grid (8 rowgroups, 8 batch) = 64 CTAs.
// Warp rg covers rows [g*32+rg*4, +4), lane covers 8 cols; smem-combine;
// 256 atomics/CTA (only 8 ops per address chip-wide — negligible contention).
// ---------------------------------------------------------------------------
__global__ void __launch_bounds__(256) kmid()
{
    __shared__ float u_s[32];
    __shared__ float part[8][256];
    const int g = blockIdx.x, b = blockIdx.y;
    const int t = threadIdx.x;
    const int rg = t >> 5, lane = t & 31;
    const int jj = lane * 8;

    GRIDDEP_WAIT();                                  // wait for pool (PDL)

    if (t < 32) u_s[t] = g_u1[b * N_ + g * 32 + t];
    __syncthreads();

    float acc[8] = {0, 0, 0, 0, 0, 0, 0, 0};
#pragma unroll
    for (int k = 0; k < 4; ++k) {
        int i = g * 32 + rg * 4 + k;
        uint4 kr = *reinterpret_cast<const uint4*>(g_K + ((size_t)b * N_ + i) * N_ + jj);
        float kf[8];
        unpack8(kr, kf);
        float uu = u_s[rg * 4 + k];
#pragma unroll
        for (int x = 0; x < 8; ++x) acc[x] = fmaf(kf[x], uu, acc[x]);
    }
#pragma unroll
    for (int x = 0; x < 8; ++x) part[rg][jj + x] = acc[x];
    __syncthreads();

    float s = 0.f;
#pragma unroll
    for (int r = 0; r < 8; ++r) s += part[r][t];
    atomicAdd(&g_KTu[b * N_ + t], s);
}

// ---------------------------------------------------------------------------
// Kernel 3: final. EXACT certificate: u2==u1 for all rows (g_conv) AND
// KTu_j + EPS == EPS for EVERY column j -> v1 uniform, fixed point proven;
// use pool's u2/cp/S. Else faithful 10-iter Sinkhorn fallback. Grid 8, 256 thr.
// ---------------------------------------------------------------------------
__global__ void __launch_bounds__(256) kfinal(
    const float* __restrict__ theta_g, const float* __restrict__ gamma_g,
    const float* __restrict__ omega_g, const float* __restrict__ alpha_g,
    const float* __restrict__ logk_g,  float* __restrict__ out)
{
    __shared__ float red[10];
    __shared__ float vsh[256], tsh[256], p_s[256], u_s[256], kv_s[256];
    __shared__ int fail;

    const int b = blockIdx.x;
    const int t = threadIdx.x;

    // ---- prolog: input loads independent of predecessors' writes ----
    float ti  = theta_g[b * N_ + t];
    float ga  = gamma_g[b * N_ + t];
    float om  = omega_g[t];
    float kap = log1pf(expf(logk_g[t]));                    // softplus

    GRIDDEP_WAIT();                                         // wait for kmid (PDL)

    // ---- exact certificate ----
    float kt = g_KTu[b * N_ + t];
    if (t == 0) fail = g_conv[b];
    __syncthreads();
    if (!(kt + EPSF == EPSF)) fail = 1;                     // column j not absorbed
    __syncthreads();

    if (!fail) {
        // -------- proven fixed point: pointwise output --------
        float S    = g_S[b];
        float Sinv = 1.0f / (S + EPSF);
        float u2   = g_u2[b * N_ + t];
        float cp   = g_cp[b * N_ + t];
        float td   = om + u2 * Sinv * cp + kap * (ga - ti);
        out[b * N_ + t] = ti + td;                          // DT=1, K_COUP=1
    } else {
        // -------- fallback: faithful 10-iter Sinkhorn from scratch --------
        const int wd = t >> 5, lane = t & 31;
        p_s[t] = g_p[b * N_ + t];
        u_s[t] = 1.0f / N_;
        vsh[t] = 1.0f / N_;
        tsh[t] = ti;
        __syncthreads();

        for (int it = 0; it < 10; ++it) {
            // u-update: 8 warps x 32 rows, K from L2
#pragma unroll 1
            for (int k = 0; k < 32; ++k) {
                int ii = wd * 32 + k;
                uint4 kr = reinterpret_cast<const uint4*>(g_K + ((size_t)b * N_ + ii) * N_)[lane];
                float acc = dot8(kr, &vsh[lane * 8]);
#pragma unroll
                for (int o = 16; o; o >>= 1) acc += __shfl_xor_sync(0xffffffffu, acc, o);
                if (lane == 0) u_s[ii] = p_s[ii] / (acc + EPSF);
            }
            __syncthreads();
            // v-update: thread t = column j
            float s = 0.f;
#pragma unroll 1
            for (int ii = 0; ii < N_; ++ii)
                s = fmaf(__bfloat162float(g_K[((size_t)b * N_ + ii) * N_ + t]), u_s[ii], s);
            __syncthreads();
            vsh[t] = (1.0f / N_) / (s + EPSF);
            __syncthreads();
        }

        // final Kv, S
#pragma unroll 1
        for (int k = 0; k < 32; ++k) {
            int ii = wd * 32 + k;
            uint4 kr = reinterpret_cast<const uint4*>(g_K + ((size_t)b * N_ + ii) * N_)[lane];
            float acc = dot8(kr, &vsh[lane * 8]);
#pragma unroll
            for (int o = 16; o; o >>= 1) acc += __shfl_xor_sync(0xffffffffu, acc, o);
            if (lane == 0) kv_s[ii] = acc;
        }
        __syncthreads();
        float S = blk_sum256(u_s[t] * kv_s[t], red);
        float Sinv = 1.0f / (S + EPSF);

        // coupling: thread t = row i
        float acc = 0.f;
#pragma unroll 1
        for (int j = 0; j < N_; ++j) {
            float kv = __bfloat162float(g_K[((size_t)b * N_ + t) * N_ + j]) * vsh[j];
            float d  = tsh[j] - ti - alpha_g[(size_t)t * N_ + j];
            acc = fmaf(kv, __sinf(d), acc);
        }
        float td = om + u_s[t] * Sinv * acc + kap * (ga - ti);
        out[b * N_ + t] = ti + td;
    }

    // -------- housekeeping for next graph replay --------
    __syncthreads();
    g_KTu[b * N_ + t] = 0.f;
    if (t == 0) { g_S[b] = 0.f; g_conv[b] = 0; }
}

// ---------------------------------------------------------------------------
extern "C" void kernel_launch(void* const* d_in, const int* in_sizes, int n_in,
                              void* d_out, int out_size)
{
    const float* theta = (const float*)d_in[0];
    const float* gamma = (const float*)d_in[1];
    const float* A     = (const float*)d_in[2];
    const float* omega = (const float*)d_in[3];
    const float* alpha = (const float*)d_in[4];
    const float* logk  = (const float*)d_in[5];
    float* out = (float*)d_out;

    dim3 g1(256, 8);
    pool_build_k<<<g1, 256>>>(A, gamma, theta, alpha);

    // kmid with PDL
    {
        cudaLaunchConfig_t cfg = {};
        cfg.gridDim  = dim3(8, 8);
        cfg.blockDim = dim3(256);
        cudaLaunchAttribute at[1];
        at[0].id = cudaLaunchAttributeProgrammaticStreamSerialization;
        at[0].val.programmaticStreamSerializationAllowed = 1;
        cfg.attrs = at;
        cfg.numAttrs = 1;
        cudaLaunchKernelEx(&cfg, kmid);
    }

    // kfinal with PDL
    {
        cudaLaunchConfig_t cfg = {};
        cfg.gridDim  = dim3(B_);
        cfg.blockDim = dim3(256);
        cudaLaunchAttribute at[1];
        at[0].id = cudaLaunchAttributeProgrammaticStreamSerialization;
        at[0].val.programmaticStreamSerializationAllowed = 1;
        cfg.attrs = at;
        cfg.numAttrs = 1;
        cudaLaunchKernelEx(&cfg, kfinal, theta, gamma, omega, alpha, logk, out);
    }
}